// round 3
// baseline (speedup 1.0000x reference)
#include <cuda_runtime.h>
#include <cuda_bf16.h>
#include <cstdint>

// Problem constants
#define MM 32
#define KK 8192
#define NN 8192
#define GROUP 128
#define KP (KK / 8)          // 1024 packed int32 rows
#define NGROUPS (KK / GROUP) // 64

// Kernel tiling
#define K_SPLIT 8
#define K_CHUNK (KK / K_SPLIT)  // 1024
#define K_SUB 128               // sub-chunk staged in SMEM (== GROUP, so one scale per sub-chunk)
#define N_TILE 256              // columns per CTA
#define THREADS 128             // each thread owns 2 columns: n0 = base+tid, n1 = n0+128

// Deterministic K-split partial sums (no atomics, no allocation)
__device__ float g_scratch[K_SPLIT * MM * NN]; // 8 MB

// ---- packed f32x2 helpers (sm_103a) ----
__device__ __forceinline__ void ffma2(unsigned long long& acc,
                                      unsigned long long a,
                                      unsigned long long b) {
    asm("fma.rn.f32x2 %0, %1, %2, %0;" : "+l"(acc) : "l"(a), "l"(b));
}

__device__ __forceinline__ unsigned long long dup2(float w) {
    unsigned long long r;
    unsigned int u = __float_as_uint(w);
    asm("mov.b64 %0, {%1, %1};" : "=l"(r) : "r"(u));
    return r;
}

__global__ void __launch_bounds__(THREADS)
marlin_gemm_kernel(const float* __restrict__ A,
                   const int*   __restrict__ qweight,
                   const float* __restrict__ scales) {
    // SMEM A sub-chunk: [K_SUB rows][32 m + 2 pad] floats -> stride 34 (17 ull, 8B aligned)
    __shared__ float Asf[K_SUB * 34];

    const int tid   = threadIdx.x;
    const int n0    = blockIdx.x * N_TILE + tid;
    const int n1    = n0 + 128;
    const int kbase = blockIdx.y * K_CHUNK;

    unsigned long long acc0[16], acc1[16];
#pragma unroll
    for (int i = 0; i < 16; i++) { acc0[i] = 0ull; acc1[i] = 0ull; }

    for (int k0 = kbase; k0 < kbase + K_CHUNK; k0 += K_SUB) {
        // Stage A[:, k0:k0+128] transposed into SMEM: Asf[kl*34 + m]
        // Thread tid handles k-column (k0 + tid); loads are coalesced across tid.
        {
            const float* ap = A + k0 + tid;
#pragma unroll
            for (int m = 0; m < MM; m++) {
                Asf[tid * 34 + m] = ap[m * KK];
            }
        }
        __syncthreads();

        // One quant group per sub-chunk (K_SUB == GROUP)
        const int g = k0 >> 7;
        const float s0 = scales[g * NN + n0];
        const float s1 = scales[g * NN + n1];
        const float b0 = -8.0f * s0;
        const float b1 = -8.0f * s1;

        const int kp0 = k0 >> 3;
#pragma unroll 2
        for (int kpl = 0; kpl < K_SUB / 8; kpl++) {  // 16 packed words
            const int q0 = qweight[(kp0 + kpl) * NN + n0];
            const int q1 = qweight[(kp0 + kpl) * NN + n1];
#pragma unroll
            for (int i = 0; i < 8; i++) {
                const float w0 = fmaf((float)((q0 >> (4 * i)) & 15), s0, b0);
                const float w1 = fmaf((float)((q1 >> (4 * i)) & 15), s1, b1);
                const unsigned long long wp0 = dup2(w0);
                const unsigned long long wp1 = dup2(w1);
                const unsigned long long* arow =
                    reinterpret_cast<const unsigned long long*>(Asf + (kpl * 8 + i) * 34);
#pragma unroll
                for (int mh = 0; mh < 16; mh++) {
                    const unsigned long long a = arow[mh];  // broadcast LDS.64
                    ffma2(acc0[mh], a, wp0);
                    ffma2(acc1[mh], a, wp1);
                }
            }
        }
        __syncthreads();
    }

    // Write deterministic partials: scratch[split][m][n]
    float* dst = g_scratch + (size_t)blockIdx.y * (MM * NN);
#pragma unroll
    for (int mh = 0; mh < 16; mh++) {
        const float2 v0 = *reinterpret_cast<const float2*>(&acc0[mh]);
        const float2 v1 = *reinterpret_cast<const float2*>(&acc1[mh]);
        dst[(2 * mh + 0) * NN + n0] = v0.x;
        dst[(2 * mh + 1) * NN + n0] = v0.y;
        dst[(2 * mh + 0) * NN + n1] = v1.x;
        dst[(2 * mh + 1) * NN + n1] = v1.y;
    }
}

__global__ void __launch_bounds__(256)
marlin_reduce_kernel(const float* __restrict__ bias, float* __restrict__ out) {
    const int idx = blockIdx.x * blockDim.x + threadIdx.x;
    if (idx >= MM * NN) return;
    const int n = idx & (NN - 1);
    float s = bias[n];
#pragma unroll
    for (int sp = 0; sp < K_SPLIT; sp++) {
        s += g_scratch[sp * (MM * NN) + idx];
    }
    out[idx] = s;
}

extern "C" void kernel_launch(void* const* d_in, const int* in_sizes, int n_in,
                              void* d_out, int out_size) {
    const float* A       = (const float*)d_in[0];
    const int*   qweight = (const int*)  d_in[1];
    const float* scales  = (const float*)d_in[2];
    const float* bias    = (const float*)d_in[3];
    float*       out     = (float*)d_out;

    dim3 grid(NN / N_TILE, K_SPLIT);
    marlin_gemm_kernel<<<grid, THREADS>>>(A, qweight, scales);
    marlin_reduce_kernel<<<(MM * NN + 255) / 256, 256>>>(bias, out);
}

// round 5
// speedup vs baseline: 2.2837x; 2.2837x over previous
#include <cuda_runtime.h>
#include <cuda_bf16.h>
#include <cstdint>

// Problem constants
#define MM 32
#define KK 8192
#define NN 8192
#define GROUP 128

// Tiling
#define K_SPLIT 8
#define K_CHUNK (KK / K_SPLIT)           // 1024
#define GROUPS_PER_CTA (K_CHUNK / GROUP) // 8
#define N_TILE 128                       // n columns per CTA (8 warps x 16)
#define WARPS 8
#define THREADS 256
#define ASTRIDE 136                      // bf16 elems per SMEM A row (128 + 8 pad)

// Deterministic K-split partials (no atomics, no allocation)
__device__ __align__(16) float g_scratch[K_SPLIT * MM * NN]; // 8 MB

__device__ __forceinline__ void ldsm_x4(uint32_t addr, uint32_t* r) {
    asm volatile("ldmatrix.sync.aligned.m8n8.x4.shared.b16 {%0,%1,%2,%3}, [%4];"
                 : "=r"(r[0]), "=r"(r[1]), "=r"(r[2]), "=r"(r[3]) : "r"(addr));
}

__device__ __forceinline__ void mma16816(float* c, const uint32_t* a, uint32_t b0, uint32_t b1) {
    asm volatile("mma.sync.aligned.m16n8k16.row.col.f32.bf16.bf16.f32 "
                 "{%0,%1,%2,%3}, {%4,%5,%6,%7}, {%8,%9}, {%0,%1,%2,%3};"
                 : "+f"(c[0]), "+f"(c[1]), "+f"(c[2]), "+f"(c[3])
                 : "r"(a[0]), "r"(a[1]), "r"(a[2]), "r"(a[3]), "r"(b0), "r"(b1));
}

// Extract byte (two consecutive int4 k-values) at bit offset sh, produce
// bf16x2 = (q_lo - 8, q_hi - 8) exactly.
// 128+q is exact in bf16 (mantissa LSB = 1 at exp 2^7): 0x4300 + q.
__device__ __forceinline__ uint32_t dq2(uint32_t w, int sh) {
    uint32_t v = (w >> sh) & 0xFFu;
    uint32_t t = v | (v << 12);                       // lo nib @bits0-3, hi nib @bits16-19
    uint32_t r = (t & 0x000F000Fu) | 0x43004300u;     // one LOP3: bf16x2(128+q)
    __nv_bfloat162 x = *reinterpret_cast<__nv_bfloat162*>(&r);
    const __nv_bfloat162 one = __float2bfloat162_rn(1.0f);
    const __nv_bfloat162 mc  = __float2bfloat162_rn(-136.0f); // exact in bf16
    __nv_bfloat162 y = __hfma2(x, one, mc);                    // exact: result in [-8,7]
    return *reinterpret_cast<uint32_t*>(&y);
}

__global__ void __launch_bounds__(THREADS)
marlin_mma_kernel(const float* __restrict__ A,
                  const int*   __restrict__ qweight,
                  const float* __restrict__ scales) {
    __shared__ __align__(16) __nv_bfloat16 sa_hi[MM * ASTRIDE];
    __shared__ __align__(16) __nv_bfloat16 sa_lo[MM * ASTRIDE];

    const int tid  = threadIdx.x;
    const int warp = tid >> 5;
    const int lane = tid & 31;
    const int lq   = lane >> 2;   // 0..7
    const int lr   = lane & 3;    // 0..3
    const int shq  = lr << 3;     // byte shift for dequant

    const int nb    = blockIdx.x * N_TILE + warp * 16; // warp n-base
    const int kbase = blockIdx.y * K_CHUNK;

    // ldmatrix per-lane addressing: row = lane&15, k-offset = 8*(lane>>4)
    const int lm_row = lane & 15;
    const int lm_k   = (lane >> 4) << 3;

    float acc[16];
#pragma unroll
    for (int i = 0; i < 16; i++) acc[i] = 0.f;

    for (int g = 0; g < GROUPS_PER_CTA; g++) {
        const int gk = kbase + g * GROUP;

        __syncthreads(); // protect previous group's SMEM reads
        // Stage A[0:32][gk:gk+128] as bf16 hi/lo split (exact to ~2^-16 rel)
        for (int i = tid; i < (MM * GROUP) / 4; i += THREADS) {
            const int row = i >> 5;
            const int k4  = (i & 31) << 2;
            const float4 a4 = *reinterpret_cast<const float4*>(A + (size_t)row * KK + gk + k4);
            float vs[4] = {a4.x, a4.y, a4.z, a4.w};
            __nv_bfloat16 h[4], l[4];
#pragma unroll
            for (int j = 0; j < 4; j++) {
                h[j] = __float2bfloat16_rn(vs[j]);
                l[j] = __float2bfloat16_rn(vs[j] - __bfloat162float(h[j]));
            }
            __nv_bfloat162* ph = reinterpret_cast<__nv_bfloat162*>(&sa_hi[row * ASTRIDE + k4]);
            __nv_bfloat162* pl = reinterpret_cast<__nv_bfloat162*>(&sa_lo[row * ASTRIDE + k4]);
            ph[0] = __nv_bfloat162(h[0], h[1]); ph[1] = __nv_bfloat162(h[2], h[3]);
            pl[0] = __nv_bfloat162(l[0], l[1]); pl[1] = __nv_bfloat162(l[2], l[3]);
        }
        __syncthreads();

        // Per-group integer partials: pc = sum_{k in group} A * (q-8)
        float pc[16];
#pragma unroll
        for (int i = 0; i < 16; i++) pc[i] = 0.f;

        const int  kp_g = gk >> 3;                 // first packed row of this group
        const int* qp0  = qweight + (size_t)kp_g * NN + nb + lq;

        // Software-pipelined qweight words (1 k-step ahead)
        uint32_t w00 = qp0[0], w01 = qp0[8], w10 = qp0[NN], w11 = qp0[NN + 8];

#pragma unroll
        for (int ks = 0; ks < 8; ks++) {
            const uint32_t cw00 = w00, cw01 = w01, cw10 = w10, cw11 = w11;
            if (ks < 7) {
                const int* qp = qp0 + (size_t)(2 * (ks + 1)) * NN;
                w00 = qp[0]; w01 = qp[8]; w10 = qp[NN]; w11 = qp[NN + 8];
            }

            // A fragments (hi/lo x 2 m-tiles) via ldmatrix
            uint32_t ah0[4], ah1[4], al0[4], al1[4];
            const int kcol = (ks << 4) + lm_k;
            ldsm_x4((uint32_t)__cvta_generic_to_shared(&sa_hi[(lm_row)      * ASTRIDE + kcol]), ah0);
            ldsm_x4((uint32_t)__cvta_generic_to_shared(&sa_hi[(16 + lm_row) * ASTRIDE + kcol]), ah1);
            ldsm_x4((uint32_t)__cvta_generic_to_shared(&sa_lo[(lm_row)      * ASTRIDE + kcol]), al0);
            ldsm_x4((uint32_t)__cvta_generic_to_shared(&sa_lo[(16 + lm_row) * ASTRIDE + kcol]), al1);

            // B fragments: exact integer (q-8) in bf16
            const uint32_t b00 = dq2(cw00, shq);  // n-tile 0, k 0-7
            const uint32_t b01 = dq2(cw10, shq);  // n-tile 0, k 8-15
            const uint32_t b10 = dq2(cw01, shq);  // n-tile 1, k 0-7
            const uint32_t b11 = dq2(cw11, shq);  // n-tile 1, k 8-15

            mma16816(pc + 0,  ah0, b00, b01);
            mma16816(pc + 0,  al0, b00, b01);
            mma16816(pc + 4,  ah1, b00, b01);
            mma16816(pc + 4,  al1, b00, b01);
            mma16816(pc + 8,  ah0, b10, b11);
            mma16816(pc + 8,  al0, b10, b11);
            mma16816(pc + 12, ah1, b10, b11);
            mma16816(pc + 12, al1, b10, b11);
        }

        // Apply per-(group, n) scale in registers
        const int gidx = gk >> 7;
        const float* sp = scales + (size_t)gidx * NN + nb + (lr << 1);
        const float s0 = __ldg(sp);
        const float s1 = __ldg(sp + 1);
        const float s2 = __ldg(sp + 8);
        const float s3 = __ldg(sp + 9);
        acc[0]  += pc[0]  * s0; acc[1]  += pc[1]  * s1; acc[2]  += pc[2]  * s0; acc[3]  += pc[3]  * s1;
        acc[4]  += pc[4]  * s0; acc[5]  += pc[5]  * s1; acc[6]  += pc[6]  * s0; acc[7]  += pc[7]  * s1;
        acc[8]  += pc[8]  * s2; acc[9]  += pc[9]  * s3; acc[10] += pc[10] * s2; acc[11] += pc[11] * s3;
        acc[12] += pc[12] * s2; acc[13] += pc[13] * s3; acc[14] += pc[14] * s2; acc[15] += pc[15] * s3;
    }

    // Write deterministic K-split partials
    float* dst = g_scratch + (size_t)blockIdx.y * (MM * NN);
#pragma unroll
    for (int mt = 0; mt < 2; mt++) {
#pragma unroll
        for (int nt = 0; nt < 2; nt++) {
            const float* c = acc + mt * 4 + nt * 8;
            const int col  = nb + nt * 8 + (lr << 1);
            const int row0 = mt * 16 + lq;
            *reinterpret_cast<float2*>(dst + (size_t)row0 * NN + col)       = make_float2(c[0], c[1]);
            *reinterpret_cast<float2*>(dst + (size_t)(row0 + 8) * NN + col) = make_float2(c[2], c[3]);
        }
    }
}

__global__ void __launch_bounds__(256)
marlin_reduce_kernel(const float* __restrict__ bias, float* __restrict__ out) {
    const int i4 = blockIdx.x * 256 + threadIdx.x;     // float4 index, 0..65535
    const float4 b = reinterpret_cast<const float4*>(bias)[i4 & (NN / 4 - 1)];
    float x = b.x, y = b.y, z = b.z, w = b.w;
#pragma unroll
    for (int sp = 0; sp < K_SPLIT; sp++) {
        const float4 v = reinterpret_cast<const float4*>(g_scratch)[sp * (MM * NN / 4) + i4];
        x += v.x; y += v.y; z += v.z; w += v.w;
    }
    reinterpret_cast<float4*>(out)[i4] = make_float4(x, y, z, w);
}

extern "C" void kernel_launch(void* const* d_in, const int* in_sizes, int n_in,
                              void* d_out, int out_size) {
    const float* A       = (const float*)d_in[0];
    const int*   qweight = (const int*)  d_in[1];
    const float* scales  = (const float*)d_in[2];
    const float* bias    = (const float*)d_in[3];
    float*       out     = (float*)d_out;

    dim3 grid(NN / N_TILE, K_SPLIT);
    marlin_mma_kernel<<<grid, THREADS>>>(A, qweight, scales);
    marlin_reduce_kernel<<<(MM * NN / 4) / 256, 256>>>(bias, out);
}

// round 6
// speedup vs baseline: 3.8542x; 1.6877x over previous
#include <cuda_runtime.h>
#include <cuda_fp16.h>
#include <cstdint>

// Problem constants
#define MM 32
#define KK 8192
#define NN 8192
#define GROUP 128

// Tiling
#define K_SPLIT 8
#define K_CHUNK (KK / K_SPLIT)           // 1024
#define GROUPS_PER_CTA (K_CHUNK / GROUP) // 8
#define WARPS 4
#define THREADS 128
#define WARP_N 32
#define N_TILE (WARPS * WARP_N)          // 128
#define ASTRIDE 136                      // fp16 elems per SMEM A row (128 + 8 pad)

// Deterministic K-split partials + pre-converted fp16 A (no atomics, no allocation)
__device__ __align__(16) float  g_scratch[K_SPLIT * MM * NN]; // 8 MB
__device__ __align__(16) __half g_A16[MM * KK];               // 512 KB

// ---------------- PTX helpers ----------------
__device__ __forceinline__ void ldsm_x4(uint32_t addr, uint32_t* r) {
    asm volatile("ldmatrix.sync.aligned.m8n8.x4.shared.b16 {%0,%1,%2,%3}, [%4];"
                 : "=r"(r[0]), "=r"(r[1]), "=r"(r[2]), "=r"(r[3]) : "r"(addr));
}

__device__ __forceinline__ void mma16816(float* c, const uint32_t* a, uint32_t b0, uint32_t b1) {
    asm volatile("mma.sync.aligned.m16n8k16.row.col.f32.f16.f16.f32 "
                 "{%0,%1,%2,%3}, {%4,%5,%6,%7}, {%8,%9}, {%0,%1,%2,%3};"
                 : "+f"(c[0]), "+f"(c[1]), "+f"(c[2]), "+f"(c[3])
                 : "r"(a[0]), "r"(a[1]), "r"(a[2]), "r"(a[3]), "r"(b0), "r"(b1));
}

// Extract byte (two int4 k-values) selected by psel, produce fp16x2 = (q_lo-8, q_hi-8) exactly.
// 1024+q is exact in fp16 (ulp=1 at 2^10): 0x6400 | q. 1032.0f16 = 0x6408 (exact).
__device__ __forceinline__ uint32_t dqh(uint32_t w, uint32_t psel) {
    uint32_t v;
    asm("prmt.b32 %0, %1, 0, %2;" : "=r"(v) : "r"(w), "r"(psel)); // clean byte -> byte0
    uint32_t t = ((v | (v << 12)) & 0x000F000Fu) | 0x64006400u;   // fp16x2(1024+q)
    __half2 x = *reinterpret_cast<__half2*>(&t);
    const __half2 c = __half2half2(__ushort_as_half(0x6408));     // 1032.0
    __half2 y = __hsub2(x, c);                                    // exact: q-8 in [-8,7]
    return *reinterpret_cast<uint32_t*>(&y);
}

__device__ __forceinline__ void cp16(uint32_t saddr, const void* gptr) {
    asm volatile("cp.async.ca.shared.global [%0], [%1], 16;" :: "r"(saddr), "l"(gptr));
}
__device__ __forceinline__ void cp_commit() {
    asm volatile("cp.async.commit_group;");
}
template <int N>
__device__ __forceinline__ void cp_wait() {
    asm volatile("cp.async.wait_group %0;" :: "n"(N));
}

// ---------------- A -> fp16 pre-convert ----------------
__global__ void __launch_bounds__(256)
a16_convert_kernel(const float* __restrict__ A) {
    const int i = blockIdx.x * 256 + threadIdx.x;   // 32768 threads, 8 elems each
    const float4* a4 = reinterpret_cast<const float4*>(A);
    const float4 x = a4[2 * i], y = a4[2 * i + 1];
    __half2 h0 = __floats2half2_rn(x.x, x.y);
    __half2 h1 = __floats2half2_rn(x.z, x.w);
    __half2 h2 = __floats2half2_rn(y.x, y.y);
    __half2 h3 = __floats2half2_rn(y.z, y.w);
    uint4 o;
    o.x = *reinterpret_cast<uint32_t*>(&h0);
    o.y = *reinterpret_cast<uint32_t*>(&h1);
    o.z = *reinterpret_cast<uint32_t*>(&h2);
    o.w = *reinterpret_cast<uint32_t*>(&h3);
    reinterpret_cast<uint4*>(g_A16)[i] = o;
}

// ---------------- GEMM ----------------
__global__ void __launch_bounds__(THREADS, 4)
marlin_mma_kernel(const int* __restrict__ qweight,
                  const float* __restrict__ scales) {
    __shared__ __align__(16) __half sa[2][MM * ASTRIDE];   // 2 x 8704 B
    __shared__ __align__(16) int    sq[2][16 * N_TILE];    // 2 x 8192 B

    const int tid  = threadIdx.x;
    const int warp = tid >> 5;
    const int lane = tid & 31;
    const int lq   = lane >> 2;   // 0..7
    const int lr   = lane & 3;    // 0..3
    const uint32_t psel = 0x4440u | (uint32_t)lr;  // PRMT: pick byte lr

    const int nb_cta = blockIdx.x * N_TILE;
    const int nb     = nb_cta + warp * WARP_N;
    const int wn     = warp * WARP_N;             // warp n-offset inside CTA tile
    const int kbase  = blockIdx.y * K_CHUNK;

    const int lm_row = lane & 15;
    const int lm_k   = (lane >> 4) << 3;

    const uint32_t sa_base = (uint32_t)__cvta_generic_to_shared(&sa[0][0]);
    const uint32_t sq_base = (uint32_t)__cvta_generic_to_shared(&sq[0][0]);

    // ---- async stage of one group's A (fp16) + qweight tile ----
    auto stage = [&](int buf, int gk) {
        const uint32_t sa_b = sa_base + (uint32_t)buf * (MM * ASTRIDE * 2);
        const uint32_t sq_b = sq_base + (uint32_t)buf * (16 * N_TILE * 4);
#pragma unroll
        for (int it = 0; it < 4; it++) {
            const int i   = it * THREADS + tid;     // 0..511
            const int row = i >> 4, c = i & 15;     // 32 rows x 16 granules
            cp16(sa_b + (uint32_t)(row * ASTRIDE + c * 8) * 2,
                 g_A16 + (size_t)row * KK + gk + c * 8);
        }
        const int kp_g = gk >> 3;
#pragma unroll
        for (int it = 0; it < 4; it++) {
            const int i   = it * THREADS + tid;     // 0..511
            const int row = i >> 5, c = i & 31;     // 16 rows x 32 granules
            cp16(sq_b + (uint32_t)(row * N_TILE + c * 4) * 4,
                 qweight + (size_t)(kp_g + row) * NN + nb_cta + c * 4);
        }
    };

    float acc[32];
#pragma unroll
    for (int i = 0; i < 32; i++) acc[i] = 0.f;

    stage(0, kbase);
    cp_commit();

    for (int g = 0; g < GROUPS_PER_CTA; g++) {
        const int gk = kbase + g * GROUP;
        if (g + 1 < GROUPS_PER_CTA) {
            stage((g + 1) & 1, gk + GROUP);
            cp_commit();
            cp_wait<1>();
        } else {
            cp_wait<0>();
        }
        __syncthreads();

        // Prefetch this group's scales (consumed after the mma loop)
        const float* sp = scales + (size_t)(gk >> 7) * NN + nb + (lr << 1);
        float s[8];
#pragma unroll
        for (int nf = 0; nf < 4; nf++) {
            s[2 * nf]     = __ldg(sp + nf * 8);
            s[2 * nf + 1] = __ldg(sp + nf * 8 + 1);
        }

        float pc[32];
#pragma unroll
        for (int i = 0; i < 32; i++) pc[i] = 0.f;

        const int buf = g & 1;
        const uint32_t sa_b = sa_base + (uint32_t)buf * (MM * ASTRIDE * 2);
        const int* q_s = &sq[buf][0];

#pragma unroll
        for (int ks = 0; ks < 8; ks++) {
            // A fragments via ldmatrix (hi-only fp16, exact-enough single term)
            uint32_t a0[4], a1[4];
            const int kcol = (ks << 4) + lm_k;
            ldsm_x4(sa_b + (uint32_t)(lm_row * ASTRIDE + kcol) * 2, a0);
            ldsm_x4(sa_b + (uint32_t)((16 + lm_row) * ASTRIDE + kcol) * 2, a1);

            // qweight words from SMEM (4-way broadcast LDS)
            const int* qr0 = q_s + (2 * ks) * N_TILE + wn + lq;
            const int* qr1 = qr0 + N_TILE;
            uint32_t b0[4], b1[4];
#pragma unroll
            for (int nf = 0; nf < 4; nf++) {
                b0[nf] = dqh((uint32_t)qr0[nf * 8], psel);  // k 0-7
                b1[nf] = dqh((uint32_t)qr1[nf * 8], psel);  // k 8-15
            }
#pragma unroll
            for (int nf = 0; nf < 4; nf++) {
                mma16816(pc + nf * 8,     a0, b0[nf], b1[nf]);
                mma16816(pc + nf * 8 + 4, a1, b0[nf], b1[nf]);
            }
        }

        // Apply per-(group, n) fp32 scales in registers
#pragma unroll
        for (int nf = 0; nf < 4; nf++) {
            const float s0 = s[2 * nf], s1 = s[2 * nf + 1];
            float* p = pc + nf * 8;
            float* a = acc + nf * 8;
            a[0] += p[0] * s0; a[1] += p[1] * s1; a[2] += p[2] * s0; a[3] += p[3] * s1;
            a[4] += p[4] * s0; a[5] += p[5] * s1; a[6] += p[6] * s0; a[7] += p[7] * s1;
        }
        __syncthreads();  // all warps done reading buf before it is restaged
    }

    // Deterministic K-split partials
    float* dst = g_scratch + (size_t)blockIdx.y * (MM * NN);
#pragma unroll
    for (int nf = 0; nf < 4; nf++) {
#pragma unroll
        for (int mt = 0; mt < 2; mt++) {
            const float* c = acc + nf * 8 + mt * 4;
            const int col  = nb + nf * 8 + (lr << 1);
            const int row0 = mt * 16 + lq;
            *reinterpret_cast<float2*>(dst + (size_t)row0 * NN + col)       = make_float2(c[0], c[1]);
            *reinterpret_cast<float2*>(dst + (size_t)(row0 + 8) * NN + col) = make_float2(c[2], c[3]);
        }
    }
}

// ---------------- split-K reduce + bias ----------------
__global__ void __launch_bounds__(256)
marlin_reduce_kernel(const float* __restrict__ bias, float* __restrict__ out) {
    const int i2 = blockIdx.x * 256 + threadIdx.x;   // float2 index, 0..131071
    const float2 b = reinterpret_cast<const float2*>(bias)[i2 & (NN / 2 - 1)];
    float x = b.x, y = b.y;
#pragma unroll
    for (int sp = 0; sp < K_SPLIT; sp++) {
        const float2 v = reinterpret_cast<const float2*>(g_scratch)[sp * (MM * NN / 2) + i2];
        x += v.x; y += v.y;
    }
    reinterpret_cast<float2*>(out)[i2] = make_float2(x, y);
}

extern "C" void kernel_launch(void* const* d_in, const int* in_sizes, int n_in,
                              void* d_out, int out_size) {
    const float* A       = (const float*)d_in[0];
    const int*   qweight = (const int*)  d_in[1];
    const float* scales  = (const float*)d_in[2];
    const float* bias    = (const float*)d_in[3];
    float*       out     = (float*)d_out;

    a16_convert_kernel<<<(MM * KK / 8) / 256, 256>>>(A);

    dim3 grid(NN / N_TILE, K_SPLIT);
    marlin_mma_kernel<<<grid, THREADS>>>(qweight, scales);

    marlin_reduce_kernel<<<(MM * NN / 2) / 256, 256>>>(bias, out);
}

// round 7
// speedup vs baseline: 3.8838x; 1.0077x over previous
#include <cuda_runtime.h>
#include <cuda_fp16.h>
#include <cstdint>

// Problem constants
#define MM 32
#define KK 8192
#define NN 8192
#define GROUP 128

// Tiling
#define K_SPLIT 8
#define K_CHUNK (KK / K_SPLIT)           // 1024
#define GROUPS_PER_CTA (K_CHUNK / GROUP) // 8
#define WARPS 4
#define THREADS 128
#define WARP_N 32
#define N_TILE (WARPS * WARP_N)          // 128
#define ASTRIDE 136                      // fp16 elems per SMEM A row (128 + 8 pad)

// Deterministic K-split partials + pre-converted fp16 A (no atomics, no allocation)
__device__ __align__(16) float  g_scratch[K_SPLIT * MM * NN]; // 8 MB
__device__ __align__(16) __half g_A16[MM * KK];               // 512 KB

// ---------------- PTX helpers ----------------
__device__ __forceinline__ void ldsm_x4(uint32_t addr, uint32_t* r) {
    asm volatile("ldmatrix.sync.aligned.m8n8.x4.shared.b16 {%0,%1,%2,%3}, [%4];"
                 : "=r"(r[0]), "=r"(r[1]), "=r"(r[2]), "=r"(r[3]) : "r"(addr));
}

__device__ __forceinline__ void lds128(uint32_t addr, uint32_t* r) {
    asm volatile("ld.shared.v4.u32 {%0,%1,%2,%3}, [%4];"
                 : "=r"(r[0]), "=r"(r[1]), "=r"(r[2]), "=r"(r[3]) : "r"(addr));
}

__device__ __forceinline__ void mma16816(float* c, const uint32_t* a, uint32_t b0, uint32_t b1) {
    asm volatile("mma.sync.aligned.m16n8k16.row.col.f32.f16.f16.f32 "
                 "{%0,%1,%2,%3}, {%4,%5,%6,%7}, {%8,%9}, {%0,%1,%2,%3};"
                 : "+f"(c[0]), "+f"(c[1]), "+f"(c[2]), "+f"(c[3])
                 : "r"(a[0]), "r"(a[1]), "r"(a[2]), "r"(a[3]), "r"(b0), "r"(b1));
}

// Extract byte (two int4 k-values) selected by psel, produce fp16x2 = (q_lo-8, q_hi-8) exactly.
// 1024+q is exact in fp16 (ulp=1 at 2^10): 0x6400 | q. 1032.0f16 = 0x6408 (exact).
__device__ __forceinline__ uint32_t dqh(uint32_t w, uint32_t psel) {
    uint32_t v;
    asm("prmt.b32 %0, %1, 0, %2;" : "=r"(v) : "r"(w), "r"(psel)); // clean byte -> byte0
    uint32_t t = ((v | (v << 12)) & 0x000F000Fu) | 0x64006400u;   // fp16x2(1024+q)
    __half2 x = *reinterpret_cast<__half2*>(&t);
    const __half2 c = __half2half2(__ushort_as_half(0x6408));     // 1032.0
    __half2 y = __hsub2(x, c);                                    // exact: q-8 in [-8,7]
    return *reinterpret_cast<uint32_t*>(&y);
}

__device__ __forceinline__ void cp16(uint32_t saddr, const void* gptr) {
    asm volatile("cp.async.cg.shared.global [%0], [%1], 16;" :: "r"(saddr), "l"(gptr));
}
__device__ __forceinline__ void cp4(uint32_t saddr, const void* gptr) {
    asm volatile("cp.async.ca.shared.global [%0], [%1], 4;" :: "r"(saddr), "l"(gptr));
}
__device__ __forceinline__ void cp_commit() {
    asm volatile("cp.async.commit_group;");
}
template <int N>
__device__ __forceinline__ void cp_wait() {
    asm volatile("cp.async.wait_group %0;" :: "n"(N));
}

// ---------------- A -> fp16 pre-convert (lightweight, 65536 threads) ----------------
__global__ void __launch_bounds__(256)
a16_convert_kernel(const float* __restrict__ A) {
    const int i = blockIdx.x * 256 + threadIdx.x;   // 0..65535, one float4 each
    const float4 x = reinterpret_cast<const float4*>(A)[i];
    __half2 h0 = __floats2half2_rn(x.x, x.y);
    __half2 h1 = __floats2half2_rn(x.z, x.w);
    uint2 o;
    o.x = *reinterpret_cast<uint32_t*>(&h0);
    o.y = *reinterpret_cast<uint32_t*>(&h1);
    reinterpret_cast<uint2*>(g_A16)[i] = o;
}

// ---------------- GEMM ----------------
// sq layout (per buffer, 2048 words): permuted so each lane's 8 words per ks are
// contiguous: off = ks*256 + warp*64 + lq*8 + rl*4 + nf
//   (rl = packed-row parity -> k-half, nf = n-fragment index)
__global__ void __launch_bounds__(THREADS, 4)
marlin_mma_kernel(const int* __restrict__ qweight,
                  const float* __restrict__ scales) {
    __shared__ __align__(16) __half sa[2][MM * ASTRIDE];   // 2 x 8704 B
    __shared__ __align__(16) int    sq[2][2048];           // 2 x 8192 B (permuted)

    const int tid  = threadIdx.x;
    const int warp = tid >> 5;
    const int lane = tid & 31;
    const int lq   = lane >> 2;   // 0..7
    const int lr   = lane & 3;    // 0..3
    const uint32_t psel = 0x4440u | (uint32_t)lr;  // PRMT: pick byte lr

    const int nb_cta = blockIdx.x * N_TILE;
    const int nb     = nb_cta + warp * WARP_N;
    const int kbase  = blockIdx.y * K_CHUNK;

    const int lm_row = lane & 15;
    const int lm_k   = (lane >> 4) << 3;

    const uint32_t sa_base = (uint32_t)__cvta_generic_to_shared(&sa[0][0]);
    const uint32_t sq_base = (uint32_t)__cvta_generic_to_shared(&sq[0][0]);

    // Permuted destination offset pieces that depend only on tid (c = tid):
    //   w = c>>5, lq8 = c&7, nf = (c>>3)&3
    const int perm_c = ((tid >> 5) << 6) | ((tid & 7) << 3) | ((tid >> 3) & 3);

    // ---- async stage of one group's A (fp16) + permuted qweight tile ----
    auto stage = [&](int buf, int gk) {
        const uint32_t sa_b = sa_base + (uint32_t)buf * (MM * ASTRIDE * 2);
        const uint32_t sq_b = sq_base + (uint32_t)buf * (2048 * 4);
#pragma unroll
        for (int it = 0; it < 4; it++) {
            const int i   = it * THREADS + tid;     // 0..511
            const int row = i >> 4, c = i & 15;     // 32 rows x 16 granules
            cp16(sa_b + (uint32_t)(row * ASTRIDE + c * 8) * 2,
                 g_A16 + (size_t)row * KK + gk + c * 8);
        }
        const int kp_g = gk >> 3;
        const int* qsrc = qweight + (size_t)kp_g * NN + nb_cta + tid;
#pragma unroll
        for (int r = 0; r < 16; r++) {              // packed rows of this group
            const int ks = r >> 1, rl = r & 1;
            const int off = ks * 256 + perm_c + rl * 4;
            cp4(sq_b + (uint32_t)off * 4, qsrc + (size_t)r * NN);
        }
    };

    float acc[32];
#pragma unroll
    for (int i = 0; i < 32; i++) acc[i] = 0.f;

    stage(0, kbase);
    cp_commit();

    for (int g = 0; g < GROUPS_PER_CTA; g++) {
        const int gk = kbase + g * GROUP;
        if (g + 1 < GROUPS_PER_CTA) {
            stage((g + 1) & 1, gk + GROUP);
            cp_commit();
            cp_wait<1>();
        } else {
            cp_wait<0>();
        }
        __syncthreads();

        // Prefetch this group's scales (consumed after the mma loop)
        const float* sp = scales + (size_t)(gk >> 7) * NN + nb + (lr << 1);
        float s[8];
#pragma unroll
        for (int nf = 0; nf < 4; nf++) {
            s[2 * nf]     = __ldg(sp + nf * 8);
            s[2 * nf + 1] = __ldg(sp + nf * 8 + 1);
        }

        float pc[32];
#pragma unroll
        for (int i = 0; i < 32; i++) pc[i] = 0.f;

        const int buf = g & 1;
        const uint32_t sa_b = sa_base + (uint32_t)buf * (MM * ASTRIDE * 2);
        const uint32_t sq_b = sq_base + (uint32_t)buf * (2048 * 4)
                            + (uint32_t)(warp * 64 + lq * 8) * 4;

#pragma unroll
        for (int ks = 0; ks < 8; ks++) {
            // A fragments via ldmatrix
            uint32_t a0[4], a1[4];
            const int kcol = (ks << 4) + lm_k;
            ldsm_x4(sa_b + (uint32_t)(lm_row * ASTRIDE + kcol) * 2, a0);
            ldsm_x4(sa_b + (uint32_t)((16 + lm_row) * ASTRIDE + kcol) * 2, a1);

            // qweight: this lane's 8 words, contiguous -> 2x LDS.128
            uint32_t q[8];
            const uint32_t qaddr = sq_b + (uint32_t)(ks * 256) * 4;
            lds128(qaddr, q);          // row 2ks   (k 0-7),  nf 0..3
            lds128(qaddr + 16, q + 4); // row 2ks+1 (k 8-15), nf 0..3

            uint32_t b0[4], b1[4];
#pragma unroll
            for (int nf = 0; nf < 4; nf++) {
                b0[nf] = dqh(q[nf], psel);
                b1[nf] = dqh(q[4 + nf], psel);
            }
#pragma unroll
            for (int nf = 0; nf < 4; nf++) {
                mma16816(pc + nf * 8,     a0, b0[nf], b1[nf]);
                mma16816(pc + nf * 8 + 4, a1, b0[nf], b1[nf]);
            }
        }

        // Apply per-(group, n) fp32 scales in registers
#pragma unroll
        for (int nf = 0; nf < 4; nf++) {
            const float s0 = s[2 * nf], s1 = s[2 * nf + 1];
            float* p = pc + nf * 8;
            float* a = acc + nf * 8;
            a[0] += p[0] * s0; a[1] += p[1] * s1; a[2] += p[2] * s0; a[3] += p[3] * s1;
            a[4] += p[4] * s0; a[5] += p[5] * s1; a[6] += p[6] * s0; a[7] += p[7] * s1;
        }
        __syncthreads();  // all warps done reading buf before it is restaged
    }

    // Deterministic K-split partials
    float* dst = g_scratch + (size_t)blockIdx.y * (MM * NN);
#pragma unroll
    for (int nf = 0; nf < 4; nf++) {
#pragma unroll
        for (int mt = 0; mt < 2; mt++) {
            const float* c = acc + nf * 8 + mt * 4;
            const int col  = nb + nf * 8 + (lr << 1);
            const int row0 = mt * 16 + lq;
            *reinterpret_cast<float2*>(dst + (size_t)row0 * NN + col)       = make_float2(c[0], c[1]);
            *reinterpret_cast<float2*>(dst + (size_t)(row0 + 8) * NN + col) = make_float2(c[2], c[3]);
        }
    }
}

// ---------------- split-K reduce + bias (131072 threads) ----------------
__global__ void __launch_bounds__(512)
marlin_reduce_kernel(const float* __restrict__ bias, float* __restrict__ out) {
    const int i2 = blockIdx.x * 512 + threadIdx.x;   // float2 index, 0..131071
    const float2 b = reinterpret_cast<const float2*>(bias)[i2 & (NN / 2 - 1)];
    float x = b.x, y = b.y;
#pragma unroll
    for (int sp = 0; sp < K_SPLIT; sp++) {
        const float2 v = reinterpret_cast<const float2*>(g_scratch)[sp * (MM * NN / 2) + i2];
        x += v.x; y += v.y;
    }
    reinterpret_cast<float2*>(out)[i2] = make_float2(x, y);
}

extern "C" void kernel_launch(void* const* d_in, const int* in_sizes, int n_in,
                              void* d_out, int out_size) {
    const float* A       = (const float*)d_in[0];
    const int*   qweight = (const int*)  d_in[1];
    const float* scales  = (const float*)d_in[2];
    const float* bias    = (const float*)d_in[3];
    float*       out     = (float*)d_out;

    a16_convert_kernel<<<(MM * KK / 4) / 256, 256>>>(A);

    dim3 grid(NN / N_TILE, K_SPLIT);
    marlin_mma_kernel<<<grid, THREADS>>>(qweight, scales);

    marlin_reduce_kernel<<<(MM * NN / 2) / 512, 512>>>(bias, out);
}